// round 6
// baseline (speedup 1.0000x reference)
#include <cuda_runtime.h>
#include <cuda_bf16.h>
#include <cstdint>

#define D 128
#define NTOT ((1 << 18) - 1)      // 262143
#define LEAF0 ((1 << 17) - 1)     // 131071
#define LDK 136                    // padded pitch (bf16) -> conflict-free ldmatrix

__device__ float g_raw[NTOT * D];          // embed output (= ret for leaves)
__device__ float g_contrib[NTOT * D];      // per-child contribution (incl. edge bias)
__device__ float g_emb_small[1023 * D];    // emb for nodes 0..1022
__device__ int   g_bucket[8 * (NTOT - 1)];
__device__ int   g_count[17 * 8];
__device__ __align__(16) __nv_bfloat16 g_Wt[9 * 2 * D * LDK];  // W^T hi/lo per matrix
__device__ int      g_bar_count;
__device__ unsigned g_bar_gen;

__device__ __forceinline__ uint32_t smem_to_u32(const void* p) {
    uint32_t a;
    asm("{ .reg .u64 t; cvta.to.shared.u64 t, %1; cvt.u32.u64 %0, t; }"
        : "=r"(a) : "l"(p));
    return a;
}

// split x into hi(bf16) + lo(bf16 residual); pack (x,y): low16=x, high16=y
__device__ __forceinline__ void split_pair(float x, float y, uint32_t& h, uint32_t& l) {
    asm("cvt.rn.bf16x2.f32 %0, %1, %2;" : "=r"(h) : "f"(y), "f"(x));
    float hx = __uint_as_float(h << 16);
    float hy = __uint_as_float(h & 0xffff0000u);
    asm("cvt.rn.bf16x2.f32 %0, %1, %2;" : "=r"(l) : "f"(y - hy), "f"(x - hx));
}

__device__ __forceinline__ void mma16816(float c[4], const uint32_t a[4],
                                         uint32_t b0, uint32_t b1) {
    asm volatile(
        "mma.sync.aligned.m16n8k16.row.col.f32.bf16.bf16.f32 "
        "{%0,%1,%2,%3}, {%4,%5,%6,%7}, {%8,%9}, {%0,%1,%2,%3};\n"
        : "+f"(c[0]), "+f"(c[1]), "+f"(c[2]), "+f"(c[3])
        : "r"(a[0]), "r"(a[1]), "r"(a[2]), "r"(a[3]), "r"(b0), "r"(b1));
}

__device__ __forceinline__ void ldsm4(uint32_t& r0, uint32_t& r1,
                                      uint32_t& r2, uint32_t& r3, uint32_t a) {
    asm volatile("ldmatrix.sync.aligned.m8n8.x4.shared.b16 {%0,%1,%2,%3}, [%4];"
                 : "=r"(r0), "=r"(r1), "=r"(r2), "=r"(r3) : "r"(a));
}

// ============================================================================
__global__ void zero_kernel() {
    int i = threadIdx.x;
    if (i < 17 * 8) g_count[i] = 0;
}

__global__ void bucket_kernel(const int* __restrict__ edges) {
    int c = blockIdx.x * blockDim.x + threadIdx.x + 2047;   // depth >= 11
    if (c >= NTOT) return;
    int d   = 31 - __clz(c + 1);
    int lev = d - 1;                    // parent level 10..16
    int M    = 1 << d;
    int base = 8 * (M - 2);
    int e = edges[c];
    int slot = atomicAdd(&g_count[lev * 8 + e], 1);
    g_bucket[base + e * M + slot] = c;
}

// W^T layout: Wt[n][k] pitch LDK, hi plane then lo plane.
__global__ void prep_B_kernel(const float* __restrict__ data_W,
                              const float* __restrict__ edge_W) {
    int m = blockIdx.x;                 // 0..7 edges, 8 = data_W
    const float* W = (m == 8) ? data_W : (edge_W + (size_t)m * D * D);
    __nv_bfloat16* dst = g_Wt + (size_t)m * 2 * D * LDK;
    for (int idx = threadIdx.x; idx < D * D; idx += blockDim.x) {
        int k = idx >> 7, n = idx & 127;
        float v = W[idx];
        __nv_bfloat16 h = __float2bfloat16(v);
        float hv = __bfloat162float(h);
        __nv_bfloat16 l = __float2bfloat16(v - hv);
        dst[n * LDK + k] = h;
        dst[D * LDK + n * LDK + k] = l;
    }
}

// ---------------------------------------------------------------------------
// mma.sync GEMM. Tile = 64 rows x 128 cols, K=128, split-bf16 (3 terms).
// 256 threads / 8 warps; warp tile m32 x n32 (2 m-frags x 4 n-frags), ldmatrix.
// mode: 0 = embed, 1 = leaf children (no relu), 2 = internal (emb on the fly)
// ---------------------------------------------------------------------------
#define SM_WH   0                       // 2*128*LDK*2 = 69632
#define SM_AH   69632                   // 2*64*LDK*2 = 34816
#define SM_BIAS 104448                  // 512
#define SM_IDS  104960                  // 256
#define SM_TOT  105216

__global__ void __launch_bounds__(256, 2)
mma_gemm_kernel(const int* __restrict__ data,
                const float* __restrict__ data_vecs,
                const int* __restrict__ counts, int bucket_base, int Mlist,
                const float* __restrict__ bias_all,
                int mode, int nb)
{
    extern __shared__ unsigned char smem[];
    __nv_bfloat16* Wh = (__nv_bfloat16*)(smem + SM_WH);
    __nv_bfloat16* Ah = (__nv_bfloat16*)(smem + SM_AH);
    float* bias_sm = (float*)(smem + SM_BIAS);
    int*   ids_sm  = (int*)(smem + SM_IDS);

    const int tid = threadIdx.x;
    const int e  = (mode == 0) ? 8 : (blockIdx.x / nb);
    const int bi = (mode == 0) ? blockIdx.x : (blockIdx.x % nb);
    const int count = (mode == 0) ? NTOT : counts[e];
    if (count == 0) return;

    // Stage W^T hi/lo (69632 B)
    {
        const uint4* src = (const uint4*)(g_Wt + (size_t)e * 2 * D * LDK);
        uint4* dst = (uint4*)Wh;
        for (int i = tid; i < 4352; i += 256) dst[i] = src[i];
    }
    {
        const float* bias = (mode == 0) ? bias_all : (bias_all + e * D);
        if (tid < D) bias_sm[tid] = bias[tid];
    }
    __syncthreads();

    const int lane = tid & 31;
    const int warp = tid >> 5;
    const int mhalf = warp & 1;          // row half: 0-31 / 32-63
    const int nquad = warp >> 1;         // col quad: nquad*32
    const int g  = lane >> 2;
    const int t2 = (lane & 3) * 2;

    const int* list = g_bucket + bucket_base + (size_t)e * Mlist;
    float* outbase = (mode == 0) ? g_raw : g_contrib;

    // ldmatrix base addresses (bytes)
    const uint32_t Abase = smem_to_u32(smem) + SM_AH;
    const uint32_t Wbase = smem_to_u32(smem) + SM_WH;
    uint32_t aAddr[2][2], wAddr[2][2];
    #pragma unroll
    for (int mt = 0; mt < 2; ++mt)
        #pragma unroll
        for (int pl = 0; pl < 2; ++pl)
            aAddr[mt][pl] = Abase +
                ((pl * 64 + mhalf * 32 + mt * 16 + (lane & 15)) * LDK
                 + (lane >> 4) * 8) * 2;
    #pragma unroll
    for (int q = 0; q < 2; ++q)
        #pragma unroll
        for (int pl = 0; pl < 2; ++pl)
            wAddr[q][pl] = Wbase +
                ((pl * 128 + nquad * 32 + q * 16 + ((lane >> 4) & 1) * 8 + (lane & 7)) * LDK
                 + ((lane >> 3) & 1) * 8) * 2;

    const int ntiles = (count + 63) >> 6;
    const int r  = tid >> 2;         // staging row 0..63
    const int cq = tid & 3;          // staging col quarter

    for (int tile = bi; tile < ntiles; tile += nb) {
        // ---------------- stage A (convert to hi/lo bf16) ----------------
        {
            int j = tile * 64 + r;
            int jj = min(j, count - 1);
            int id;
            const float4 *s0, *s1 = nullptr, *s2 = nullptr;
            if (mode == 0) {
                id = jj;
                s0 = (const float4*)(data_vecs + (size_t)__ldg(&data[jj]) * D);
            } else {
                id = list[jj];
                s0 = (const float4*)(g_raw + (size_t)id * D);
                if (mode == 2) {
                    s1 = (const float4*)(g_contrib + (size_t)(2 * id + 1) * D);
                    s2 = (const float4*)(g_contrib + (size_t)(2 * id + 2) * D);
                }
            }
            if (cq == 0) ids_sm[r] = id;
            #pragma unroll
            for (int i = 0; i < 8; ++i) {
                int c = cq * 32 + i * 4;
                float4 v = s0[c >> 2];
                if (mode == 2) {
                    float4 a = s1[c >> 2], b = s2[c >> 2];
                    v.x = fmaxf((v.x + a.x + b.x) * (1.f / 3.f), 0.f);
                    v.y = fmaxf((v.y + a.y + b.y) * (1.f / 3.f), 0.f);
                    v.z = fmaxf((v.z + a.z + b.z) * (1.f / 3.f), 0.f);
                    v.w = fmaxf((v.w + a.w + b.w) * (1.f / 3.f), 0.f);
                }
                uint32_t h0, l0, h1, l1;
                split_pair(v.x, v.y, h0, l0);
                split_pair(v.z, v.w, h1, l1);
                *(uint2*)(Ah + r * LDK + c) = make_uint2(h0, h1);
                *(uint2*)(Ah + 64 * LDK + r * LDK + c) = make_uint2(l0, l1);
            }
        }
        __syncthreads();

        // ---------------- MMA main loop ----------------
        float acc[2][4][4];
        #pragma unroll
        for (int mt = 0; mt < 2; ++mt)
            #pragma unroll
            for (int nt = 0; nt < 4; ++nt)
                #pragma unroll
                for (int i = 0; i < 4; ++i) acc[mt][nt][i] = 0.f;

        #pragma unroll
        for (int ks = 0; ks < 8; ++ks) {
            const uint32_t kb = ks * 32;   // 16 elems * 2B
            uint32_t ah[2][4], al[2][4];
            #pragma unroll
            for (int mt = 0; mt < 2; ++mt) {
                ldsm4(ah[mt][0], ah[mt][1], ah[mt][2], ah[mt][3], aAddr[mt][0] + kb);
                ldsm4(al[mt][0], al[mt][1], al[mt][2], al[mt][3], aAddr[mt][1] + kb);
            }
            uint32_t bh[4][2], bl[4][2];
            #pragma unroll
            for (int q = 0; q < 2; ++q) {
                ldsm4(bh[2 * q][0], bh[2 * q][1], bh[2 * q + 1][0], bh[2 * q + 1][1],
                      wAddr[q][0] + kb);
                ldsm4(bl[2 * q][0], bl[2 * q][1], bl[2 * q + 1][0], bl[2 * q + 1][1],
                      wAddr[q][1] + kb);
            }
            #pragma unroll
            for (int mt = 0; mt < 2; ++mt)
                #pragma unroll
                for (int nt = 0; nt < 4; ++nt) {
                    mma16816(acc[mt][nt], ah[mt], bh[nt][0], bh[nt][1]);   // hi*Whi
                    mma16816(acc[mt][nt], al[mt], bh[nt][0], bh[nt][1]);   // lo*Whi
                    mma16816(acc[mt][nt], ah[mt], bl[nt][0], bl[nt][1]);   // hi*Wlo
                }
        }

        // ---------------- epilogue ----------------
        #pragma unroll
        for (int mt = 0; mt < 2; ++mt) {
            int rr = mhalf * 32 + mt * 16 + g;
            int id0 = ids_sm[rr];
            int id1 = ids_sm[rr + 8];
            float* o0 = outbase + (size_t)id0 * D;
            float* o1 = outbase + (size_t)id1 * D;
            #pragma unroll
            for (int nt = 0; nt < 4; ++nt) {
                int n0 = nquad * 32 + nt * 8 + t2;
                float b0 = bias_sm[n0], b1 = bias_sm[n0 + 1];
                *(float2*)(o0 + n0) = make_float2(acc[mt][nt][0] + b0,
                                                  acc[mt][nt][1] + b1);
                *(float2*)(o1 + n0) = make_float2(acc[mt][nt][2] + b0,
                                                  acc[mt][nt][3] + b1);
            }
        }
        __syncthreads();
    }
}

// ---------------------------------------------------------------------------
// Fused small levels (l = 9..0) with software grid barrier.
// ---------------------------------------------------------------------------
#define NBL 128
__device__ __forceinline__ void grid_bar() {
    __syncthreads();
    if (threadIdx.x == 0) {
        unsigned gen = *((volatile unsigned*)&g_bar_gen);
        __threadfence();
        if (atomicAdd(&g_bar_count, 1) == NBL - 1) {
            g_bar_count = 0;
            __threadfence();
            atomicAdd(&g_bar_gen, 1u);
        } else {
            while (*((volatile unsigned*)&g_bar_gen) == gen) { }
        }
        __threadfence();
    }
    __syncthreads();
}

__global__ void small_levels_kernel(const int* __restrict__ edges,
                                    const float* __restrict__ edge_W,
                                    const float* __restrict__ edge_b)
{
    __shared__ float v1[D], v2[D];
    const int tid = threadIdx.x;
    for (int l = 9; l >= 0; --l) {
        const int npar = 1 << l, p0 = npar - 1;
        for (int p = p0 + blockIdx.x; p < p0 + npar; p += NBL) {
            const int c1 = 2 * p + 1, c2 = 2 * p + 2;
            float r1, r2;
            if (l == 9) {
                r1 = fmaxf((g_raw[(size_t)c1 * D + tid]
                            + g_contrib[(size_t)(2 * c1 + 1) * D + tid]
                            + g_contrib[(size_t)(2 * c1 + 2) * D + tid]) * (1.f / 3.f), 0.f);
                r2 = fmaxf((g_raw[(size_t)c2 * D + tid]
                            + g_contrib[(size_t)(2 * c2 + 1) * D + tid]
                            + g_contrib[(size_t)(2 * c2 + 2) * D + tid]) * (1.f / 3.f), 0.f);
            } else {
                r1 = fmaxf(g_emb_small[(size_t)c1 * D + tid], 0.f);
                r2 = fmaxf(g_emb_small[(size_t)c2 * D + tid], 0.f);
            }
            v1[tid] = r1; v2[tid] = r2;
            const int e1 = edges[c1], e2 = edges[c2];
            __syncthreads();
            const float* W1 = edge_W + (size_t)e1 * D * D + tid;
            const float* W2 = edge_W + (size_t)e2 * D * D + tid;
            float acc = edge_b[e1 * D + tid] + edge_b[e2 * D + tid];
            #pragma unroll 8
            for (int k = 0; k < D; ++k)
                acc += v1[k] * W1[k * D] + v2[k] * W2[k * D];
            float h = (g_raw[(size_t)p * D + tid] + acc) * (1.f / 3.f);
            g_emb_small[(size_t)p * D + tid] = h;
            __syncthreads();
        }
        grid_bar();
    }
}

// ---------------------------------------------------------------------------
// Scores
// ---------------------------------------------------------------------------
__global__ void score_kernel(const float* __restrict__ score_W,
                             float* __restrict__ out)
{
    __shared__ float sW[D];
    const int tid = threadIdx.x;
    if (tid < D) sW[tid] = score_W[tid];
    __syncthreads();
    const int w = tid >> 5, lane = tid & 31;
    const float4 s4 = ((const float4*)sW)[lane];
    const int gw = blockIdx.x * 8 + w;
    const int nw = gridDim.x * 8;
    for (int node = gw; node < NTOT; node += nw) {
        float4 v;
        if (node >= LEAF0) {
            v = ((const float4*)(g_raw + (size_t)node * D))[lane];
        } else if (node >= 1023) {
            float4 r  = ((const float4*)(g_raw     + (size_t)node * D))[lane];
            float4 a  = ((const float4*)(g_contrib + (size_t)(2 * node + 1) * D))[lane];
            float4 b  = ((const float4*)(g_contrib + (size_t)(2 * node + 2) * D))[lane];
            v = make_float4((r.x + a.x + b.x) * (1.f / 3.f),
                            (r.y + a.y + b.y) * (1.f / 3.f),
                            (r.z + a.z + b.z) * (1.f / 3.f),
                            (r.w + a.w + b.w) * (1.f / 3.f));
        } else {
            v = ((const float4*)(g_emb_small + (size_t)node * D))[lane];
        }
        float d = v.x * s4.x + v.y * s4.y + v.z * s4.z + v.w * s4.w;
        #pragma unroll
        for (int off = 16; off; off >>= 1)
            d += __shfl_xor_sync(0xffffffffu, d, off);
        if (lane == 0) out[node] = d;
    }
}

extern "C" void kernel_launch(void* const* d_in, const int* in_sizes, int n_in,
                              void* d_out, int out_size)
{
    const int*   data      = (const int*)  d_in[0];
    const int*   edges     = (const int*)  d_in[1];
    const float* data_vecs = (const float*)d_in[2];
    const float* data_W    = (const float*)d_in[3];
    const float* data_b    = (const float*)d_in[4];
    const float* edge_W    = (const float*)d_in[5];
    const float* edge_b    = (const float*)d_in[6];
    const float* score_W   = (const float*)d_in[7];
    float* out = (float*)d_out;
    (void)in_sizes; (void)n_in; (void)out_size;

    cudaFuncSetAttribute(mma_gemm_kernel,
                         cudaFuncAttributeMaxDynamicSharedMemorySize, SM_TOT);

    int* d_count;
    cudaGetSymbolAddress((void**)&d_count, g_count);

    zero_kernel<<<1, 160>>>();
    bucket_kernel<<<(NTOT - 2047 + 255) / 256, 256>>>(edges);
    prep_B_kernel<<<9, 256>>>(data_W, edge_W);

    // Embed (mode 0): 2 blocks/SM
    mma_gemm_kernel<<<296, 256, SM_TOT>>>(data, data_vecs,
                                          nullptr, 0, 0,
                                          data_b, 0, 296);

    // Large levels: l = 16 .. 10
    for (int l = 16; l >= 10; --l) {
        int dd = l + 1;
        int M2 = 1 << dd;                 // children at this level
        int base = 8 * (M2 - 2);
        int tiles_pe = ((M2 >> 3) + 63) >> 6;   // expected 64-row tiles per edge
        int nb = tiles_pe; if (nb < 1) nb = 1; if (nb > 36) nb = 36;
        mma_gemm_kernel<<<8 * nb, 256, SM_TOT>>>(nullptr, nullptr,
                                                 d_count + l * 8, base, M2,
                                                 edge_b, (l == 16) ? 1 : 2, nb);
    }

    // Small levels fused (l = 9..0)
    small_levels_kernel<<<NBL, 128>>>(edges, edge_W, edge_b);

    score_kernel<<<592, 256>>>(score_W, out);
}

// round 7
// speedup vs baseline: 1.3632x; 1.3632x over previous
#include <cuda_runtime.h>
#include <cuda_bf16.h>
#include <cstdint>

#define D 128
#define NTOT ((1 << 18) - 1)      // 262143
#define LEAF0 ((1 << 17) - 1)     // 131071
#define LDK 136                    // padded pitch (bf16) -> conflict-free ldmatrix

__device__ float g_raw[NTOT * D];          // embed output (= ret for leaves)
__device__ float g_contrib[NTOT * D];      // per-child contribution (incl. edge bias)
__device__ float g_emb_small[1023 * D];    // emb for nodes 0..1022
__device__ int   g_bucket[8 * (NTOT - 1)];
__device__ int   g_count[17 * 8];
__device__ __align__(16) __nv_bfloat16 g_Wt[9 * 2 * D * LDK];  // W^T hi/lo per matrix
__device__ int      g_bar_count;
__device__ unsigned g_bar_gen;

__device__ __forceinline__ uint32_t smem_to_u32(const void* p) {
    uint32_t a;
    asm("{ .reg .u64 t; cvta.to.shared.u64 t, %1; cvt.u32.u64 %0, t; }"
        : "=r"(a) : "l"(p));
    return a;
}

// split x into hi(bf16) + lo(bf16 residual); pack (x,y): low16=x, high16=y
__device__ __forceinline__ void split_pair(float x, float y, uint32_t& h, uint32_t& l) {
    asm("cvt.rn.bf16x2.f32 %0, %1, %2;" : "=r"(h) : "f"(y), "f"(x));
    float hx = __uint_as_float(h << 16);
    float hy = __uint_as_float(h & 0xffff0000u);
    asm("cvt.rn.bf16x2.f32 %0, %1, %2;" : "=r"(l) : "f"(y - hy), "f"(x - hx));
}

__device__ __forceinline__ void mma16816(float c[4], const uint32_t a[4],
                                         uint32_t b0, uint32_t b1) {
    asm volatile(
        "mma.sync.aligned.m16n8k16.row.col.f32.bf16.bf16.f32 "
        "{%0,%1,%2,%3}, {%4,%5,%6,%7}, {%8,%9}, {%0,%1,%2,%3};\n"
        : "+f"(c[0]), "+f"(c[1]), "+f"(c[2]), "+f"(c[3])
        : "r"(a[0]), "r"(a[1]), "r"(a[2]), "r"(a[3]), "r"(b0), "r"(b1));
}

__device__ __forceinline__ void ldsm4(uint32_t& r0, uint32_t& r1,
                                      uint32_t& r2, uint32_t& r3, uint32_t a) {
    asm volatile("ldmatrix.sync.aligned.m8n8.x4.shared.b16 {%0,%1,%2,%3}, [%4];"
                 : "=r"(r0), "=r"(r1), "=r"(r2), "=r"(r3) : "r"(a));
}

// ============================================================================
__global__ void zero_kernel() {
    int i = threadIdx.x;
    if (i < 17 * 8) g_count[i] = 0;
}

__global__ void bucket_kernel(const int* __restrict__ edges) {
    int c = blockIdx.x * blockDim.x + threadIdx.x + 2047;   // depth >= 11
    if (c >= NTOT) return;
    int d   = 31 - __clz(c + 1);
    int lev = d - 1;                    // parent level 10..16
    int M    = 1 << d;
    int base = 8 * (M - 2);
    int e = edges[c];
    int slot = atomicAdd(&g_count[lev * 8 + e], 1);
    g_bucket[base + e * M + slot] = c;
}

// W^T layout: Wt[n][k] pitch LDK, hi plane then lo plane.
__global__ void prep_B_kernel(const float* __restrict__ data_W,
                              const float* __restrict__ edge_W) {
    int m = blockIdx.x;                 // 0..7 edges, 8 = data_W
    const float* W = (m == 8) ? data_W : (edge_W + (size_t)m * D * D);
    __nv_bfloat16* dst = g_Wt + (size_t)m * 2 * D * LDK;
    for (int idx = threadIdx.x; idx < D * D; idx += blockDim.x) {
        int k = idx >> 7, n = idx & 127;
        float v = W[idx];
        __nv_bfloat16 h = __float2bfloat16(v);
        float hv = __bfloat162float(h);
        __nv_bfloat16 l = __float2bfloat16(v - hv);
        dst[n * LDK + k] = h;
        dst[D * LDK + n * LDK + k] = l;
    }
}

// ---------------------------------------------------------------------------
// mma.sync GEMM. Tile = 64 rows x 128 cols, K=128, split-bf16 (3 terms).
// 256 threads / 8 warps; warp tile m32 x n32 (2 m-frags x 4 n-frags), ldmatrix.
// mode: 0 = embed, 1 = leaf children (no relu), 2 = internal (emb on the fly)
// ---------------------------------------------------------------------------
#define SM_WH   0                       // 2*128*LDK*2 = 69632
#define SM_AH   69632                   // 2*64*LDK*2 = 34816
#define SM_BIAS 104448                  // 512
#define SM_IDS  104960                  // 256
#define SM_TOT  105216

__global__ void __launch_bounds__(256, 2)
mma_gemm_kernel(const int* __restrict__ data,
                const float* __restrict__ data_vecs,
                const int* __restrict__ counts, int bucket_base, int Mlist,
                const float* __restrict__ bias_all,
                int mode, int nb)
{
    extern __shared__ unsigned char smem[];
    __nv_bfloat16* Wh = (__nv_bfloat16*)(smem + SM_WH);
    __nv_bfloat16* Ah = (__nv_bfloat16*)(smem + SM_AH);
    float* bias_sm = (float*)(smem + SM_BIAS);
    int*   ids_sm  = (int*)(smem + SM_IDS);

    const int tid = threadIdx.x;
    const int e  = (mode == 0) ? 8 : (blockIdx.x / nb);
    const int bi = (mode == 0) ? blockIdx.x : (blockIdx.x % nb);
    const int count = (mode == 0) ? NTOT : counts[e];
    if (count == 0) return;

    // Stage W^T hi/lo (69632 B)
    {
        const uint4* src = (const uint4*)(g_Wt + (size_t)e * 2 * D * LDK);
        uint4* dst = (uint4*)Wh;
        for (int i = tid; i < 4352; i += 256) dst[i] = src[i];
    }
    {
        const float* bias = (mode == 0) ? bias_all : (bias_all + e * D);
        if (tid < D) bias_sm[tid] = bias[tid];
    }
    __syncthreads();

    const int lane = tid & 31;
    const int warp = tid >> 5;
    const int mhalf = warp & 1;          // row half: 0-31 / 32-63
    const int nquad = warp >> 1;         // col quad: nquad*32
    const int g  = lane >> 2;
    const int t2 = (lane & 3) * 2;

    const int* list = g_bucket + bucket_base + (size_t)e * Mlist;
    float* outbase = (mode == 0) ? g_raw : g_contrib;

    // ldmatrix base addresses (bytes)
    const uint32_t Abase = smem_to_u32(smem) + SM_AH;
    const uint32_t Wbase = smem_to_u32(smem) + SM_WH;
    uint32_t aAddr[2][2], wAddr[2][2];
    #pragma unroll
    for (int mt = 0; mt < 2; ++mt)
        #pragma unroll
        for (int pl = 0; pl < 2; ++pl)
            aAddr[mt][pl] = Abase +
                ((pl * 64 + mhalf * 32 + mt * 16 + (lane & 15)) * LDK
                 + (lane >> 4) * 8) * 2;
    #pragma unroll
    for (int q = 0; q < 2; ++q)
        #pragma unroll
        for (int pl = 0; pl < 2; ++pl)
            wAddr[q][pl] = Wbase +
                ((pl * 128 + nquad * 32 + q * 16 + ((lane >> 4) & 1) * 8 + (lane & 7)) * LDK
                 + ((lane >> 3) & 1) * 8) * 2;

    const int ntiles = (count + 63) >> 6;
    const int r  = tid >> 2;         // staging row 0..63
    const int cq = tid & 3;          // staging col quarter

    for (int tile = bi; tile < ntiles; tile += nb) {
        // ---------------- stage A (convert to hi/lo bf16) ----------------
        {
            int j = tile * 64 + r;
            int jj = min(j, count - 1);
            int id;
            const float4 *s0, *s1 = nullptr, *s2 = nullptr;
            if (mode == 0) {
                id = jj;
                s0 = (const float4*)(data_vecs + (size_t)__ldg(&data[jj]) * D);
            } else {
                id = list[jj];
                s0 = (const float4*)(g_raw + (size_t)id * D);
                if (mode == 2) {
                    s1 = (const float4*)(g_contrib + (size_t)(2 * id + 1) * D);
                    s2 = (const float4*)(g_contrib + (size_t)(2 * id + 2) * D);
                }
            }
            if (cq == 0) ids_sm[r] = id;
            #pragma unroll
            for (int i = 0; i < 8; ++i) {
                int c = cq * 32 + i * 4;
                float4 v = s0[c >> 2];
                if (mode == 2) {
                    float4 a = s1[c >> 2], b = s2[c >> 2];
                    v.x = fmaxf((v.x + a.x + b.x) * (1.f / 3.f), 0.f);
                    v.y = fmaxf((v.y + a.y + b.y) * (1.f / 3.f), 0.f);
                    v.z = fmaxf((v.z + a.z + b.z) * (1.f / 3.f), 0.f);
                    v.w = fmaxf((v.w + a.w + b.w) * (1.f / 3.f), 0.f);
                }
                uint32_t h0, l0, h1, l1;
                split_pair(v.x, v.y, h0, l0);
                split_pair(v.z, v.w, h1, l1);
                *(uint2*)(Ah + r * LDK + c) = make_uint2(h0, h1);
                *(uint2*)(Ah + 64 * LDK + r * LDK + c) = make_uint2(l0, l1);
            }
        }
        __syncthreads();

        // ---------------- MMA main loop ----------------
        float acc[2][4][4];
        #pragma unroll
        for (int mt = 0; mt < 2; ++mt)
            #pragma unroll
            for (int nt = 0; nt < 4; ++nt)
                #pragma unroll
                for (int i = 0; i < 4; ++i) acc[mt][nt][i] = 0.f;

        #pragma unroll
        for (int ks = 0; ks < 8; ++ks) {
            const uint32_t kb = ks * 32;   // 16 elems * 2B
            uint32_t ah[2][4], al[2][4];
            #pragma unroll
            for (int mt = 0; mt < 2; ++mt) {
                ldsm4(ah[mt][0], ah[mt][1], ah[mt][2], ah[mt][3], aAddr[mt][0] + kb);
                ldsm4(al[mt][0], al[mt][1], al[mt][2], al[mt][3], aAddr[mt][1] + kb);
            }
            uint32_t bh[4][2], bl[4][2];
            #pragma unroll
            for (int q = 0; q < 2; ++q) {
                ldsm4(bh[2 * q][0], bh[2 * q][1], bh[2 * q + 1][0], bh[2 * q + 1][1],
                      wAddr[q][0] + kb);
                ldsm4(bl[2 * q][0], bl[2 * q][1], bl[2 * q + 1][0], bl[2 * q + 1][1],
                      wAddr[q][1] + kb);
            }
            #pragma unroll
            for (int mt = 0; mt < 2; ++mt)
                #pragma unroll
                for (int nt = 0; nt < 4; ++nt) {
                    mma16816(acc[mt][nt], ah[mt], bh[nt][0], bh[nt][1]);   // hi*Whi
                    mma16816(acc[mt][nt], al[mt], bh[nt][0], bh[nt][1]);   // lo*Whi
                    mma16816(acc[mt][nt], ah[mt], bl[nt][0], bl[nt][1]);   // hi*Wlo
                }
        }

        // ---------------- epilogue ----------------
        #pragma unroll
        for (int mt = 0; mt < 2; ++mt) {
            int rr = mhalf * 32 + mt * 16 + g;
            int id0 = ids_sm[rr];
            int id1 = ids_sm[rr + 8];
            float* o0 = outbase + (size_t)id0 * D;
            float* o1 = outbase + (size_t)id1 * D;
            #pragma unroll
            for (int nt = 0; nt < 4; ++nt) {
                int n0 = nquad * 32 + nt * 8 + t2;
                float b0 = bias_sm[n0], b1 = bias_sm[n0 + 1];
                *(float2*)(o0 + n0) = make_float2(acc[mt][nt][0] + b0,
                                                  acc[mt][nt][1] + b1);
                *(float2*)(o1 + n0) = make_float2(acc[mt][nt][2] + b0,
                                                  acc[mt][nt][3] + b1);
            }
        }
        __syncthreads();
    }
}

// ---------------------------------------------------------------------------
// Fused small levels (l = 9..0) with software grid barrier.
// ---------------------------------------------------------------------------
#define NBL 128
__device__ __forceinline__ void grid_bar() {
    __syncthreads();
    if (threadIdx.x == 0) {
        unsigned gen = *((volatile unsigned*)&g_bar_gen);
        __threadfence();
        if (atomicAdd(&g_bar_count, 1) == NBL - 1) {
            g_bar_count = 0;
            __threadfence();
            atomicAdd(&g_bar_gen, 1u);
        } else {
            while (*((volatile unsigned*)&g_bar_gen) == gen) { }
        }
        __threadfence();
    }
    __syncthreads();
}

__global__ void small_levels_kernel(const int* __restrict__ edges,
                                    const float* __restrict__ edge_W,
                                    const float* __restrict__ edge_b)
{
    __shared__ float v1[D], v2[D];
    const int tid = threadIdx.x;
    for (int l = 9; l >= 0; --l) {
        const int npar = 1 << l, p0 = npar - 1;
        for (int p = p0 + blockIdx.x; p < p0 + npar; p += NBL) {
            const int c1 = 2 * p + 1, c2 = 2 * p + 2;
            float r1, r2;
            if (l == 9) {
                r1 = fmaxf((g_raw[(size_t)c1 * D + tid]
                            + g_contrib[(size_t)(2 * c1 + 1) * D + tid]
                            + g_contrib[(size_t)(2 * c1 + 2) * D + tid]) * (1.f / 3.f), 0.f);
                r2 = fmaxf((g_raw[(size_t)c2 * D + tid]
                            + g_contrib[(size_t)(2 * c2 + 1) * D + tid]
                            + g_contrib[(size_t)(2 * c2 + 2) * D + tid]) * (1.f / 3.f), 0.f);
            } else {
                r1 = fmaxf(g_emb_small[(size_t)c1 * D + tid], 0.f);
                r2 = fmaxf(g_emb_small[(size_t)c2 * D + tid], 0.f);
            }
            v1[tid] = r1; v2[tid] = r2;
            const int e1 = edges[c1], e2 = edges[c2];
            __syncthreads();
            const float* W1 = edge_W + (size_t)e1 * D * D + tid;
            const float* W2 = edge_W + (size_t)e2 * D * D + tid;
            float acc = edge_b[e1 * D + tid] + edge_b[e2 * D + tid];
            #pragma unroll 8
            for (int k = 0; k < D; ++k)
                acc += v1[k] * W1[k * D] + v2[k] * W2[k * D];
            float h = (g_raw[(size_t)p * D + tid] + acc) * (1.f / 3.f);
            g_emb_small[(size_t)p * D + tid] = h;
            __syncthreads();
        }
        grid_bar();
    }
}

// ---------------------------------------------------------------------------
// Scores
// ---------------------------------------------------------------------------
__global__ void score_kernel(const float* __restrict__ score_W,
                             float* __restrict__ out)
{
    __shared__ float sW[D];
    const int tid = threadIdx.x;
    if (tid < D) sW[tid] = score_W[tid];
    __syncthreads();
    const int w = tid >> 5, lane = tid & 31;
    const float4 s4 = ((const float4*)sW)[lane];
    const int gw = blockIdx.x * 8 + w;
    const int nw = gridDim.x * 8;
    for (int node = gw; node < NTOT; node += nw) {
        float4 v;
        if (node >= LEAF0) {
            v = ((const float4*)(g_raw + (size_t)node * D))[lane];
        } else if (node >= 1023) {
            float4 r  = ((const float4*)(g_raw     + (size_t)node * D))[lane];
            float4 a  = ((const float4*)(g_contrib + (size_t)(2 * node + 1) * D))[lane];
            float4 b  = ((const float4*)(g_contrib + (size_t)(2 * node + 2) * D))[lane];
            v = make_float4((r.x + a.x + b.x) * (1.f / 3.f),
                            (r.y + a.y + b.y) * (1.f / 3.f),
                            (r.z + a.z + b.z) * (1.f / 3.f),
                            (r.w + a.w + b.w) * (1.f / 3.f));
        } else {
            v = ((const float4*)(g_emb_small + (size_t)node * D))[lane];
        }
        float d = v.x * s4.x + v.y * s4.y + v.z * s4.z + v.w * s4.w;
        #pragma unroll
        for (int off = 16; off; off >>= 1)
            d += __shfl_xor_sync(0xffffffffu, d, off);
        if (lane == 0) out[node] = d;
    }
}

extern "C" void kernel_launch(void* const* d_in, const int* in_sizes, int n_in,
                              void* d_out, int out_size)
{
    const int*   data      = (const int*)  d_in[0];
    const int*   edges     = (const int*)  d_in[1];
    const float* data_vecs = (const float*)d_in[2];
    const float* data_W    = (const float*)d_in[3];
    const float* data_b    = (const float*)d_in[4];
    const float* edge_W    = (const float*)d_in[5];
    const float* edge_b    = (const float*)d_in[6];
    const float* score_W   = (const float*)d_in[7];
    float* out = (float*)d_out;
    (void)in_sizes; (void)n_in; (void)out_size;

    cudaFuncSetAttribute(mma_gemm_kernel,
                         cudaFuncAttributeMaxDynamicSharedMemorySize, SM_TOT);

    int* d_count;
    cudaGetSymbolAddress((void**)&d_count, g_count);

    zero_kernel<<<1, 160>>>();
    bucket_kernel<<<(NTOT - 2047 + 255) / 256, 256>>>(edges);
    prep_B_kernel<<<9, 256>>>(data_W, edge_W);

    // Embed (mode 0): 2 blocks/SM
    mma_gemm_kernel<<<296, 256, SM_TOT>>>(data, data_vecs,
                                          nullptr, 0, 0,
                                          data_b, 0, 296);

    // Large levels: l = 16 .. 10
    for (int l = 16; l >= 10; --l) {
        int dd = l + 1;
        int M2 = 1 << dd;                 // children at this level
        int base = 8 * (M2 - 2);
        int tiles_pe = ((M2 >> 3) + 63) >> 6;   // expected 64-row tiles per edge
        int nb = tiles_pe; if (nb < 1) nb = 1; if (nb > 36) nb = 36;
        mma_gemm_kernel<<<8 * nb, 256, SM_TOT>>>(nullptr, nullptr,
                                                 d_count + l * 8, base, M2,
                                                 edge_b, (l == 16) ? 1 : 2, nb);
    }

    // Small levels fused (l = 9..0)
    small_levels_kernel<<<NBL, 128>>>(edges, edge_W, edge_b);

    score_kernel<<<592, 256>>>(score_W, out);
}

// round 8
// speedup vs baseline: 1.7745x; 1.3016x over previous
#include <cuda_runtime.h>
#include <cuda_bf16.h>
#include <cstdint>

#define D 128
#define NTOT ((1 << 18) - 1)      // 262143
#define LEAF0 ((1 << 17) - 1)     // 131071
#define LDK 136                    // bf16 pitch -> conflict-free ldmatrix
#define LDS_ST 144                 // fp32 stage pitch -> conflict-free float4 reads

__device__ float g_raw[NTOT * D];          // embed output (= ret for leaves)
__device__ float g_emb[NTOT * D];          // emb for all internal nodes
__device__ float g_contrib[NTOT * D];      // per-child contribution (incl. edge bias)
__device__ int   g_bucket[8 * (NTOT - 1)];
__device__ int   g_count[17 * 8];
__device__ __align__(16) __nv_bfloat16 g_Wt[9 * 2 * D * LDK];  // W^T hi/lo per matrix
__device__ int      g_bar_count;
__device__ unsigned g_bar_gen;

__device__ __forceinline__ uint32_t smem_to_u32(const void* p) {
    uint32_t a;
    asm("{ .reg .u64 t; cvta.to.shared.u64 t, %1; cvt.u32.u64 %0, t; }"
        : "=r"(a) : "l"(p));
    return a;
}
__device__ __forceinline__ void cp16(uint32_t dst, const void* src) {
    asm volatile("cp.async.ca.shared.global [%0], [%1], 16;"
                 :: "r"(dst), "l"(src) : "memory");
}
__device__ __forceinline__ void cp_commit() {
    asm volatile("cp.async.commit_group;" ::: "memory");
}
__device__ __forceinline__ void cp_wait0() {
    asm volatile("cp.async.wait_group 0;" ::: "memory");
}

// split x into hi(bf16) + lo(bf16 residual); pack (x,y): low16=x, high16=y
__device__ __forceinline__ void split_pair(float x, float y, uint32_t& h, uint32_t& l) {
    asm("cvt.rn.bf16x2.f32 %0, %1, %2;" : "=r"(h) : "f"(y), "f"(x));
    float hx = __uint_as_float(h << 16);
    float hy = __uint_as_float(h & 0xffff0000u);
    asm("cvt.rn.bf16x2.f32 %0, %1, %2;" : "=r"(l) : "f"(y - hy), "f"(x - hx));
}
__device__ __forceinline__ void mma16816(float c[4], const uint32_t a[4],
                                         uint32_t b0, uint32_t b1) {
    asm volatile(
        "mma.sync.aligned.m16n8k16.row.col.f32.bf16.bf16.f32 "
        "{%0,%1,%2,%3}, {%4,%5,%6,%7}, {%8,%9}, {%0,%1,%2,%3};\n"
        : "+f"(c[0]), "+f"(c[1]), "+f"(c[2]), "+f"(c[3])
        : "r"(a[0]), "r"(a[1]), "r"(a[2]), "r"(a[3]), "r"(b0), "r"(b1));
}
__device__ __forceinline__ void ldsm4(uint32_t& r0, uint32_t& r1,
                                      uint32_t& r2, uint32_t& r3, uint32_t a) {
    asm volatile("ldmatrix.sync.aligned.m8n8.x4.shared.b16 {%0,%1,%2,%3}, [%4];"
                 : "=r"(r0), "=r"(r1), "=r"(r2), "=r"(r3) : "r"(a));
}

// ============================================================================
__global__ void zero_kernel() {
    int i = threadIdx.x;
    if (i < 17 * 8) g_count[i] = 0;
}

__global__ void bucket_kernel(const int* __restrict__ edges) {
    int c = blockIdx.x * blockDim.x + threadIdx.x + 2047;   // depth >= 11
    if (c >= NTOT) return;
    int d   = 31 - __clz(c + 1);
    int lev = d - 1;                    // parent level 10..16
    int M    = 1 << d;
    int base = 8 * (M - 2);
    int e = edges[c];
    int slot = atomicAdd(&g_count[lev * 8 + e], 1);
    g_bucket[base + e * M + slot] = c;
}

// W^T layout: Wt[n][k] pitch LDK, hi plane then lo plane.
__global__ void prep_B_kernel(const float* __restrict__ data_W,
                              const float* __restrict__ edge_W) {
    int m = blockIdx.x;                 // 0..7 edges, 8 = data_W
    const float* W = (m == 8) ? data_W : (edge_W + (size_t)m * D * D);
    __nv_bfloat16* dst = g_Wt + (size_t)m * 2 * D * LDK;
    for (int idx = threadIdx.x; idx < D * D; idx += blockDim.x) {
        int k = idx >> 7, n = idx & 127;
        float v = W[idx];
        __nv_bfloat16 h = __float2bfloat16(v);
        float hv = __bfloat162float(h);
        __nv_bfloat16 l = __float2bfloat16(v - hv);
        dst[n * LDK + k] = h;
        dst[D * LDK + n * LDK + k] = l;
    }
}

// ---------------------------------------------------------------------------
// Pipelined mma.sync GEMM. Tile = 128 rows x 128 cols, K = 128, split-bf16.
// 512 threads / 16 warps; warp tile m32 x n32; cp.async double-staged A.
// mode: 0 = embed (gather data_vecs), 1 = leaf children (g_raw, no relu),
//       2 = internal children (g_emb, relu on convert)
// ---------------------------------------------------------------------------
#define SM_WH    0                      // 69632
#define SM_AH    69632                  // 69632 (hi plane + lo plane @ +128*LDK)
#define SM_STAGE 139264                 // 128 * 144 * 4 = 73728
#define SM_BIAS  212992                 // 512
#define SM_IDS   213504                 // 2 * 128 * 4 = 1024
#define SM_TOT   214528

__global__ void __launch_bounds__(512, 1)
mma_gemm_kernel(const int* __restrict__ data,
                const float* __restrict__ data_vecs,
                const float* __restrict__ srcarr,
                const int* __restrict__ counts, int bucket_base, int Mlist,
                const float* __restrict__ bias_all,
                int mode, int nb)
{
    extern __shared__ unsigned char smem[];
    __nv_bfloat16* Wh = (__nv_bfloat16*)(smem + SM_WH);
    __nv_bfloat16* Ah = (__nv_bfloat16*)(smem + SM_AH);
    float* stage_f = (float*)(smem + SM_STAGE);
    float* bias_sm = (float*)(smem + SM_BIAS);
    int*   ids_sm  = (int*)(smem + SM_IDS);

    const int tid = threadIdx.x;
    const int e  = (mode == 0) ? 8 : (blockIdx.x / nb);
    const int bi = (mode == 0) ? blockIdx.x : (blockIdx.x % nb);
    const int count = (mode == 0) ? NTOT : counts[e];
    if (count == 0) return;
    const int ntiles = (count + 127) >> 7;
    if (bi >= ntiles) return;
    const int relu = (mode == 2);

    const uint32_t smem_u = smem_to_u32(smem);
    const int* list = g_bucket + bucket_base + (size_t)e * Mlist;
    float* outbase = (mode == 0) ? g_raw : g_contrib;

    const int sr = tid >> 2;            // staging row 0..127
    const int sq = tid & 3;             // staging quarter

    // ---- prologue: issue fetch of first tile ----
    {
        int jj = min(bi * 128 + sr, count - 1);
        int id = (mode == 0) ? jj : list[jj];
        if (sq == 0) ids_sm[sr] = id;
        const float* src = (mode == 0)
            ? data_vecs + (size_t)__ldg(&data[jj]) * D
            : srcarr + (size_t)id * D;
        uint32_t dst = smem_u + SM_STAGE + (sr * LDS_ST + sq * 4) * 4;
        #pragma unroll
        for (int i = 0; i < 8; ++i)
            cp16(dst + i * 64, src + sq * 4 + i * 16);
        cp_commit();
    }

    // ---- stage W^T hi/lo + bias (overlaps the cp.async above) ----
    {
        const uint4* src = (const uint4*)(g_Wt + (size_t)e * 2 * D * LDK);
        uint4* dst = (uint4*)Wh;
        for (int i = tid; i < 4352; i += 512) dst[i] = src[i];
        const float* bias = (mode == 0) ? bias_all : (bias_all + e * D);
        if (tid < D) bias_sm[tid] = bias[tid];
    }
    cp_wait0();
    __syncthreads();

    // ---- convert helper (stage fp32 -> Ah hi/lo bf16) ----
    auto convert = [&]() {
        const float* st = stage_f + sr * LDS_ST + sq * 4;
        #pragma unroll
        for (int i = 0; i < 8; ++i) {
            float4 v = *(const float4*)(st + i * 16);
            if (relu) {
                v.x = fmaxf(v.x, 0.f); v.y = fmaxf(v.y, 0.f);
                v.z = fmaxf(v.z, 0.f); v.w = fmaxf(v.w, 0.f);
            }
            uint32_t h0, l0, h1, l1;
            split_pair(v.x, v.y, h0, l0);
            split_pair(v.z, v.w, h1, l1);
            int c = sq * 4 + i * 16;
            *(uint2*)(Ah + sr * LDK + c) = make_uint2(h0, h1);
            *(uint2*)(Ah + 128 * LDK + sr * LDK + c) = make_uint2(l0, l1);
        }
    };
    convert();
    __syncthreads();

    // ---- warp tiling ----
    const int lane = tid & 31;
    const int warp = tid >> 5;
    const int mq = warp & 3;             // m quarter (32 rows)
    const int nq = warp >> 2;            // n quarter (32 cols)
    const int g  = lane >> 2;
    const int t2 = (lane & 3) * 2;

    const uint32_t Abase = smem_u + SM_AH;
    const uint32_t Wbase = smem_u + SM_WH;
    uint32_t aAddr[2][2], wAddr[2][2];
    #pragma unroll
    for (int mt = 0; mt < 2; ++mt)
        #pragma unroll
        for (int pl = 0; pl < 2; ++pl)
            aAddr[mt][pl] = Abase +
                ((pl * 128 + mq * 32 + mt * 16 + (lane & 15)) * LDK
                 + (lane >> 4) * 8) * 2;
    #pragma unroll
    for (int q = 0; q < 2; ++q)
        #pragma unroll
        for (int pl = 0; pl < 2; ++pl)
            wAddr[q][pl] = Wbase +
                ((pl * 128 + nq * 32 + q * 16 + ((lane >> 4) & 1) * 8 + (lane & 7)) * LDK
                 + ((lane >> 3) & 1) * 8) * 2;

    int pp = 0;
    for (int tile = bi; tile < ntiles; tile += nb) {
        const int nxt = tile + nb;

        // ---- issue fetch for next tile (overlaps MMA below) ----
        if (nxt < ntiles) {
            int jj = min(nxt * 128 + sr, count - 1);
            int id = (mode == 0) ? jj : list[jj];
            if (sq == 0) ids_sm[(pp ^ 1) * 128 + sr] = id;
            const float* src = (mode == 0)
                ? data_vecs + (size_t)__ldg(&data[jj]) * D
                : srcarr + (size_t)id * D;
            uint32_t dst = smem_u + SM_STAGE + (sr * LDS_ST + sq * 4) * 4;
            #pragma unroll
            for (int i = 0; i < 8; ++i)
                cp16(dst + i * 64, src + sq * 4 + i * 16);
            cp_commit();
        }

        // ---- MMA main loop ----
        float acc[2][4][4];
        #pragma unroll
        for (int mt = 0; mt < 2; ++mt)
            #pragma unroll
            for (int nt = 0; nt < 4; ++nt)
                #pragma unroll
                for (int i = 0; i < 4; ++i) acc[mt][nt][i] = 0.f;

        #pragma unroll
        for (int ks = 0; ks < 8; ++ks) {
            const uint32_t kb = ks * 32;
            uint32_t ah[2][4], al[2][4];
            #pragma unroll
            for (int mt = 0; mt < 2; ++mt) {
                ldsm4(ah[mt][0], ah[mt][1], ah[mt][2], ah[mt][3], aAddr[mt][0] + kb);
                ldsm4(al[mt][0], al[mt][1], al[mt][2], al[mt][3], aAddr[mt][1] + kb);
            }
            uint32_t bh[4][2], bl[4][2];
            #pragma unroll
            for (int q = 0; q < 2; ++q) {
                ldsm4(bh[2 * q][0], bh[2 * q][1], bh[2 * q + 1][0], bh[2 * q + 1][1],
                      wAddr[q][0] + kb);
                ldsm4(bl[2 * q][0], bl[2 * q][1], bl[2 * q + 1][0], bl[2 * q + 1][1],
                      wAddr[q][1] + kb);
            }
            #pragma unroll
            for (int mt = 0; mt < 2; ++mt)
                #pragma unroll
                for (int nt = 0; nt < 4; ++nt) {
                    mma16816(acc[mt][nt], ah[mt], bh[nt][0], bh[nt][1]);
                    mma16816(acc[mt][nt], al[mt], bh[nt][0], bh[nt][1]);
                    mma16816(acc[mt][nt], ah[mt], bl[nt][0], bl[nt][1]);
                }
        }

        // ---- epilogue (independent of pending cp.async) ----
        #pragma unroll
        for (int mt = 0; mt < 2; ++mt) {
            int rr = mq * 32 + mt * 16 + g;
            int id0 = ids_sm[pp * 128 + rr];
            int id1 = ids_sm[pp * 128 + rr + 8];
            float* o0 = outbase + (size_t)id0 * D;
            float* o1 = outbase + (size_t)id1 * D;
            #pragma unroll
            for (int nt = 0; nt < 4; ++nt) {
                int n0 = nq * 32 + nt * 8 + t2;
                float b0 = bias_sm[n0], b1 = bias_sm[n0 + 1];
                *(float2*)(o0 + n0) = make_float2(acc[mt][nt][0] + b0,
                                                  acc[mt][nt][1] + b1);
                *(float2*)(o1 + n0) = make_float2(acc[mt][nt][2] + b0,
                                                  acc[mt][nt][3] + b1);
            }
        }

        if (nxt < ntiles) {
            cp_wait0();
            __syncthreads();        // stage ready; all warps done with Ah
            convert();
            __syncthreads();        // Ah ready for next MMA
            pp ^= 1;
        }
    }
}

// emb[p] = (raw[p] + contrib[2p+1] + contrib[2p+2]) / 3
__global__ void combine_kernel(int p0, int npar) {
    int idx = blockIdx.x * blockDim.x + threadIdx.x;
    if (idx >= npar * 32) return;
    int i = idx >> 5, q = idx & 31;
    int p = p0 + i;
    float4 r  = ((const float4*)(g_raw     + (size_t)p * D))[q];
    float4 c1 = ((const float4*)(g_contrib + (size_t)(2 * p + 1) * D))[q];
    float4 c2 = ((const float4*)(g_contrib + (size_t)(2 * p + 2) * D))[q];
    float4 h = make_float4((r.x + c1.x + c2.x) * (1.f / 3.f),
                           (r.y + c1.y + c2.y) * (1.f / 3.f),
                           (r.z + c1.z + c2.z) * (1.f / 3.f),
                           (r.w + c1.w + c2.w) * (1.f / 3.f));
    ((float4*)(g_emb + (size_t)p * D))[q] = h;
}

// ---------------------------------------------------------------------------
// Fused small levels (l = 9..0) with software grid barrier.
// ---------------------------------------------------------------------------
#define NBL 128
__device__ __forceinline__ void grid_bar() {
    __syncthreads();
    if (threadIdx.x == 0) {
        unsigned gen = *((volatile unsigned*)&g_bar_gen);
        __threadfence();
        if (atomicAdd(&g_bar_count, 1) == NBL - 1) {
            g_bar_count = 0;
            __threadfence();
            atomicAdd(&g_bar_gen, 1u);
        } else {
            while (*((volatile unsigned*)&g_bar_gen) == gen) { }
        }
        __threadfence();
    }
    __syncthreads();
}

__global__ void small_levels_kernel(const int* __restrict__ edges,
                                    const float* __restrict__ edge_W,
                                    const float* __restrict__ edge_b)
{
    __shared__ float v1[D], v2[D];
    const int tid = threadIdx.x;
    for (int l = 9; l >= 0; --l) {
        const int npar = 1 << l, p0 = npar - 1;
        for (int p = p0 + blockIdx.x; p < p0 + npar; p += NBL) {
            const int c1 = 2 * p + 1, c2 = 2 * p + 2;
            v1[tid] = fmaxf(g_emb[(size_t)c1 * D + tid], 0.f);
            v2[tid] = fmaxf(g_emb[(size_t)c2 * D + tid], 0.f);
            const int e1 = edges[c1], e2 = edges[c2];
            __syncthreads();
            const float* W1 = edge_W + (size_t)e1 * D * D + tid;
            const float* W2 = edge_W + (size_t)e2 * D * D + tid;
            float acc = edge_b[e1 * D + tid] + edge_b[e2 * D + tid];
            #pragma unroll 8
            for (int k = 0; k < D; ++k)
                acc += v1[k] * W1[k * D] + v2[k] * W2[k * D];
            float h = (g_raw[(size_t)p * D + tid] + acc) * (1.f / 3.f);
            g_emb[(size_t)p * D + tid] = h;
            __syncthreads();
        }
        grid_bar();
    }
}

// ---------------------------------------------------------------------------
// Scores: internal -> g_emb, leaves -> g_raw
// ---------------------------------------------------------------------------
__global__ void score_kernel(const float* __restrict__ score_W,
                             float* __restrict__ out)
{
    __shared__ float sW[D];
    const int tid = threadIdx.x;
    if (tid < D) sW[tid] = score_W[tid];
    __syncthreads();
    const int w = tid >> 5, lane = tid & 31;
    const float4 s4 = ((const float4*)sW)[lane];
    const int gw = blockIdx.x * 8 + w;
    const int nw = gridDim.x * 8;
    for (int node = gw; node < NTOT; node += nw) {
        const float* src = (node < LEAF0) ? g_emb : g_raw;
        float4 v = ((const float4*)(src + (size_t)node * D))[lane];
        float d = v.x * s4.x + v.y * s4.y + v.z * s4.z + v.w * s4.w;
        #pragma unroll
        for (int off = 16; off; off >>= 1)
            d += __shfl_xor_sync(0xffffffffu, d, off);
        if (lane == 0) out[node] = d;
    }
}

extern "C" void kernel_launch(void* const* d_in, const int* in_sizes, int n_in,
                              void* d_out, int out_size)
{
    const int*   data      = (const int*)  d_in[0];
    const int*   edges     = (const int*)  d_in[1];
    const float* data_vecs = (const float*)d_in[2];
    const float* data_W    = (const float*)d_in[3];
    const float* data_b    = (const float*)d_in[4];
    const float* edge_W    = (const float*)d_in[5];
    const float* edge_b    = (const float*)d_in[6];
    const float* score_W   = (const float*)d_in[7];
    float* out = (float*)d_out;
    (void)in_sizes; (void)n_in; (void)out_size;

    cudaFuncSetAttribute(mma_gemm_kernel,
                         cudaFuncAttributeMaxDynamicSharedMemorySize, SM_TOT);

    int* d_count;
    cudaGetSymbolAddress((void**)&d_count, g_count);
    float* d_raw;
    cudaGetSymbolAddress((void**)&d_raw, g_raw);
    float* d_emb;
    cudaGetSymbolAddress((void**)&d_emb, g_emb);

    zero_kernel<<<1, 160>>>();
    bucket_kernel<<<(NTOT - 2047 + 255) / 256, 256>>>(edges);
    prep_B_kernel<<<9, 256>>>(data_W, edge_W);

    // Embed (mode 0)
    mma_gemm_kernel<<<148, 512, SM_TOT>>>(data, data_vecs, nullptr,
                                          nullptr, 0, 0,
                                          data_b, 0, 148);

    // Large levels: l = 16 .. 10  (GEMM over children, then combine)
    for (int l = 16; l >= 10; --l) {
        int dd = l + 1;
        int M2 = 1 << dd;                 // children count at this level
        int base = 8 * (M2 - 2);
        int npar = 1 << l;
        int p0 = npar - 1;
        int tiles_pe = (M2 / 8 + 127) >> 7;   // expected 128-row tiles per edge
        int nb = tiles_pe; if (nb < 1) nb = 1; if (nb > 18) nb = 18;
        const float* srcarr = (l == 16) ? d_raw : d_emb;
        mma_gemm_kernel<<<8 * nb, 512, SM_TOT>>>(nullptr, nullptr, srcarr,
                                                 d_count + l * 8, base, M2,
                                                 edge_b, (l == 16) ? 1 : 2, nb);
        combine_kernel<<<(npar * 32 + 255) / 256, 256>>>(p0, npar);
    }

    // Small levels fused (l = 9..0)
    small_levels_kernel<<<NBL, 128>>>(edges, edge_W, edge_b);

    score_kernel<<<592, 256>>>(score_W, out);
}